// round 11
// baseline (speedup 1.0000x reference)
#include <cuda_runtime.h>
#include <cuda_fp16.h>
#include <cstdint>

#define NPIX 4096
#define CB   256
#define BQ   4
#define TM   128
#define SKP  32    // packed fp16 K-tile stride in halves (bulk-copy layout)
#define SXS  68    // qk saD-chunk stride (floats)
#define SPS  132   // pass-2 staging stride (floats)

// Scratch (device globals — no runtime allocation allowed)
__device__ float  g_qk[BQ][32][NPIX];        // q (float), [d][n]
__device__ __half g_kh[BQ][NPIX][32];        // k transposed [m][d], fp16 (1 MB)
__device__ float  g_v[BQ][CB][NPIX];         // only when gamma != 0

#define LOG2E 1.4426950408889634f

__device__ __forceinline__ float tf32r(float v) {
    uint32_t u;
    asm("cvt.rna.tf32.f32 %0, %1;" : "=r"(u) : "f"(v));
    return __uint_as_float(u);
}
__device__ __forceinline__ float ex2f(float x) {
    float r;
    asm("ex2.approx.f32 %0, %1;" : "=f"(r) : "f"(x));
    return r;
}

// ---- bulk-copy + mbarrier primitives ----
__device__ __forceinline__ uint32_t s2u(const void* p) {
    return (uint32_t)__cvta_generic_to_shared(p);
}
__device__ __forceinline__ void mbar_init(uint32_t a, uint32_t cnt) {
    asm volatile("mbarrier.init.shared.b64 [%0], %1;" :: "r"(a), "r"(cnt) : "memory");
}
__device__ __forceinline__ void mbar_expect_tx(uint32_t a, uint32_t bytes) {
    asm volatile("mbarrier.arrive.expect_tx.shared.b64 _, [%0], %1;"
                 :: "r"(a), "r"(bytes) : "memory");
}
__device__ __forceinline__ void bulk_g2s(uint32_t sdst, const void* g,
                                         uint32_t bytes, uint32_t mbar) {
    asm volatile(
        "cp.async.bulk.shared::cta.global.mbarrier::complete_tx::bytes "
        "[%0], [%1], %2, [%3];"
        :: "r"(sdst), "l"(g), "r"(bytes), "r"(mbar) : "memory");
}
__device__ __forceinline__ void mbar_wait(uint32_t a, uint32_t parity) {
    asm volatile(
        "{\n\t.reg .pred P;\n"
        "W%=:\n\tmbarrier.try_wait.parity.acquire.cta.shared::cta.b64 P, [%0], %1, 0x989680;\n"
        "\t@P bra D%=;\n\tbra W%=;\n"
        "D%=:\n\t}\n"
        :: "r"(a), "r"(parity) : "memory");
}

// ---- mma helpers ----
__device__ __forceinline__ void mma_tf32(float& c0, float& c1, float& c2, float& c3,
                                         const float a[4], float b0, float b1)
{
    asm volatile(
        "mma.sync.aligned.m16n8k8.row.col.f32.tf32.tf32.f32 "
        "{%0,%1,%2,%3}, {%4,%5,%6,%7}, {%8,%9}, {%0,%1,%2,%3};"
        : "+f"(c0), "+f"(c1), "+f"(c2), "+f"(c3)
        : "r"(__float_as_uint(a[0])), "r"(__float_as_uint(a[1])),
          "r"(__float_as_uint(a[2])), "r"(__float_as_uint(a[3])),
          "r"(__float_as_uint(b0)), "r"(__float_as_uint(b1)));
}
__device__ __forceinline__ void mma_f16(float& c0, float& c1, float& c2, float& c3,
                                        const uint32_t a[4], uint32_t b0, uint32_t b1)
{
    asm volatile(
        "mma.sync.aligned.m16n8k16.row.col.f32.f16.f16.f32 "
        "{%0,%1,%2,%3}, {%4,%5,%6,%7}, {%8,%9}, {%0,%1,%2,%3};"
        : "+f"(c0), "+f"(c1), "+f"(c2), "+f"(c3)
        : "r"(a[0]), "r"(a[1]), "r"(a[2]), "r"(a[3]), "r"(b0), "r"(b1));
}
// f16 accumulators: D = {row lq (2 halves), row lq+8 (2 halves)}
__device__ __forceinline__ void mma_f16acc(uint32_t& d0, uint32_t& d1,
                                           const uint32_t a[4], uint32_t b0, uint32_t b1)
{
    asm volatile(
        "mma.sync.aligned.m16n8k16.row.col.f16.f16.f16.f16 "
        "{%0,%1}, {%2,%3,%4,%5}, {%6,%7}, {%0,%1};"
        : "+r"(d0), "+r"(d1)
        : "r"(a[0]), "r"(a[1]), "r"(a[2]), "r"(a[3]), "r"(b0), "r"(b1));
}
__device__ __forceinline__ uint32_t packh(float lo, float hi) {
    __half2 h = __floats2half2_rn(lo, hi);
    return *(uint32_t*)&h;
}

// ---------------------------------------------------------------------------
// Kernel A (tf32 mma): q = Wq·sa_D + bq (float, [d][n]),
//                      k = Wk·sa_D + bk (fp16, [m][d] transposed)
// ---------------------------------------------------------------------------
__global__ __launch_bounds__(256, 2) void qk_kernel(
    const float* __restrict__ saD,
    const float* __restrict__ Wq, const float* __restrict__ bq,
    const float* __restrict__ Wk, const float* __restrict__ bk)
{
    extern __shared__ float sm[];
    float* sW = sm;                 // 64 x 258 (tf32-rounded W)
    float* sX = sm + 64 * 258;      // 64 x SXS (tf32-rounded saD chunk)

    int b  = blockIdx.y;
    int n0 = blockIdx.x * 64;
    int t  = threadIdx.x, w = t >> 5, l = t & 31;
    int lq = l >> 2, lr = l & 3;
    int wd = w & 3, wn = w >> 2;

    for (int i = t; i < 64 * 256; i += 256) {
        int d = i >> 8, c = i & 255;
        float v = (d < 32) ? Wq[d * 256 + c] : Wk[(d - 32) * 256 + c];
        sW[d * 258 + c] = tf32r(v);
    }
    __syncthreads();

    float acc[4][4];
#pragma unroll
    for (int j = 0; j < 4; j++)
#pragma unroll
        for (int i = 0; i < 4; i++) acc[j][i] = 0.f;

    for (int c0 = 0; c0 < 256; c0 += 64) {
        __syncthreads();
#pragma unroll
        for (int r = 0; r < 4; r++) {
            int f  = t + 256 * r;
            int cc = f >> 4, nn = (f & 15) << 2;
            float4 v = *(const float4*)&saD[(size_t)(b * 256 + c0 + cc) * NPIX + n0 + nn];
            v.x = tf32r(v.x); v.y = tf32r(v.y); v.z = tf32r(v.z); v.w = tf32r(v.w);
            *(float4*)&sX[cc * SXS + nn] = v;
        }
        __syncthreads();
#pragma unroll
        for (int kk = 0; kk < 8; kk++) {
            int ca = c0 + kk * 8;
            float a[4];
            a[0] = sW[(wd * 16 + lq) * 258 + ca + lr];
            a[1] = sW[(wd * 16 + 8 + lq) * 258 + ca + lr];
            a[2] = sW[(wd * 16 + lq) * 258 + ca + lr + 4];
            a[3] = sW[(wd * 16 + 8 + lq) * 258 + ca + lr + 4];
#pragma unroll
            for (int j = 0; j < 4; j++) {
                float b0 = sX[(kk * 8 + lr) * SXS + wn * 32 + j * 8 + lq];
                float b1 = sX[(kk * 8 + lr + 4) * SXS + wn * 32 + j * 8 + lq];
                mma_tf32(acc[j][0], acc[j][1], acc[j][2], acc[j][3], a, b0, b1);
            }
        }
    }

    // q epilogue (wd 0,1 -> d rows 0..31)
    if (wd < 2) {
        int d = wd * 16 + lq;
        float bias0 = bq[d], bias1 = bq[d + 8];
#pragma unroll
        for (int j = 0; j < 4; j++) {
            int n = n0 + wn * 32 + j * 8 + lr * 2;
            *(float2*)&g_qk[b][d][n] =
                make_float2(acc[j][0] + bias0, acc[j][1] + bias0);
            *(float2*)&g_qk[b][d + 8][n] =
                make_float2(acc[j][2] + bias1, acc[j][3] + bias1);
        }
    }

    // k epilogue: stage fp16 [n][d] in smem (reuse sX), coalesced out
    __syncthreads();
    __half* sT = (__half*)sX;   // 64 x 40 halves
    if (wd >= 2) {
        int dk = (wd - 2) * 16 + lq;
        float bias0 = bk[dk], bias1 = bk[dk + 8];
#pragma unroll
        for (int j = 0; j < 4; j++) {
            int nl = wn * 32 + j * 8 + lr * 2;
            sT[nl * 40 + dk]           = __float2half(acc[j][0] + bias0);
            sT[(nl + 1) * 40 + dk]     = __float2half(acc[j][1] + bias0);
            sT[nl * 40 + dk + 8]       = __float2half(acc[j][2] + bias1);
            sT[(nl + 1) * 40 + dk + 8] = __float2half(acc[j][3] + bias1);
        }
    }
    __syncthreads();
    {
        int r = t >> 2, p = t & 3;
        uint4 v = *(uint4*)&sT[r * 40 + p * 8];
        *(uint4*)&g_kh[b][n0 + r][p * 8] = v;
    }
}

// ---------------------------------------------------------------------------
// Kernel B: fused energy + softmax + attention.
// Bulk-TMA double-buffered K tiles. Pass 1: f16-accum mma -> h2exp2 direct.
// Pass 2: SAME compute structure as R10 (2jj x 4rg chains), but results go
// through a CTA staging tile sP[64][SPS]; drained with coalesced STG.128
// (4 wf/instr vs 8 wf per scattered STG.64 — 4x wavefront cut).
// ---------------------------------------------------------------------------
__global__ __launch_bounds__(256, 2) void attn_kernel(float* __restrict__ att)
{
    extern __shared__ float sm[];
    float*  sQ   = sm;                            // 64*33 floats
    __half* sK   = (__half*)(sm + 64 * 33);       // 2 bufs x 128*SKP halves (16 KB)
    float*  sP   = (float*)(sK + 2 * 128 * SKP);  // 64 x SPS floats (33 KB)
    float*  sSum = sP + 64 * SPS;                 // 8*64
    float*  sInv = sSum + 8 * 64;                 // 64
    uint64_t* mbars = (uint64_t*)(sInv + 64);     // 2 mbarriers

    int b  = blockIdx.y;
    int n0 = blockIdx.x * 64;
    int t  = threadIdx.x, w = t >> 5, l = t & 31;
    int lq = l >> 2, lr = l & 3;
    int j0 = 2 * w;

    const float*  qg  = &g_qk[b][0][0];
    const __half* khg = &g_kh[b][0][0];

    uint32_t mb0 = s2u(&mbars[0]), mb1 = s2u(&mbars[1]);
    uint32_t skbase = s2u(sK);

    if (t == 0) { mbar_init(mb0, 1); mbar_init(mb1, 1); }

    // Q tile [64 n][32 d], transposed, pre-scaled by log2e
    for (int i = t; i < 64 * 32; i += 256) {
        int n = i & 63, d = i >> 6;
        sQ[n * 33 + d] = qg[(size_t)d * NPIX + n0 + n] * LOG2E;
    }
    __syncthreads();   // covers mbarrier init + sQ

    auto issue = [&](int tile) {
        if (t == 0) {
            uint32_t mb = (tile & 1) ? mb1 : mb0;
            mbar_expect_tx(mb, 8192);
            bulk_g2s(skbase + (tile & 1) * 8192, khg + (size_t)tile * TM * SKP,
                     8192, mb);
        }
    };

    int ph0 = 0, ph1 = 0;
    issue(0); issue(1);

    // A fragments fp16: 4 row-groups x 2 k16-chunks x 4 regs (both passes)
    uint32_t aH[4][2][4];
#pragma unroll
    for (int rg = 0; rg < 4; rg++) {
        int r = rg * 16 + lq;
#pragma unroll
        for (int kk = 0; kk < 2; kk++) {
            int c = kk * 16 + lr * 2;
            aH[rg][kk][0] = packh(sQ[r * 33 + c],           sQ[r * 33 + c + 1]);
            aH[rg][kk][1] = packh(sQ[(r + 8) * 33 + c],     sQ[(r + 8) * 33 + c + 1]);
            aH[rg][kk][2] = packh(sQ[r * 33 + c + 8],       sQ[r * 33 + c + 9]);
            aH[rg][kk][3] = packh(sQ[(r + 8) * 33 + c + 8], sQ[(r + 8) * 33 + c + 9]);
        }
    }

    // ======== pass 1: denominators (f16-accum mma -> h2exp2 direct) ========
    float s[4][2];
#pragma unroll
    for (int rg = 0; rg < 4; rg++) s[rg][0] = s[rg][1] = 0.f;

    for (int tile = 0; tile < 32; tile++) {
        int bsel = tile & 1;
        if (bsel) { mbar_wait(mb1, ph1); ph1 ^= 1; }
        else      { mbar_wait(mb0, ph0); ph0 ^= 1; }
        __half* cur = sK + bsel * 128 * SKP;

        __half2 ha[4][2];
#pragma unroll
        for (int rg = 0; rg < 4; rg++) {
            ha[rg][0] = __floats2half2_rn(0.f, 0.f);
            ha[rg][1] = __floats2half2_rn(0.f, 0.f);
        }
#pragma unroll
        for (int jj = 0; jj < 2; jj++) {
            int j = j0 + jj;
            uint32_t b0[2], b1[2];
#pragma unroll
            for (int kk = 0; kk < 2; kk++) {
                b0[kk] = *(uint32_t*)&cur[(j * 8 + lq) * SKP + kk * 16 + lr * 2];
                b1[kk] = *(uint32_t*)&cur[(j * 8 + lq) * SKP + kk * 16 + lr * 2 + 8];
            }
#pragma unroll
            for (int rg = 0; rg < 4; rg++) {
                uint32_t d0 = 0, d1 = 0;
                mma_f16acc(d0, d1, aH[rg][0], b0[0], b1[0]);
                mma_f16acc(d0, d1, aH[rg][1], b0[1], b1[1]);
                ha[rg][0] = __hadd2(ha[rg][0], h2exp2(*(__half2*)&d0));
                ha[rg][1] = __hadd2(ha[rg][1], h2exp2(*(__half2*)&d1));
            }
        }
#pragma unroll
        for (int rg = 0; rg < 4; rg++) {
            float2 f0 = __half22float2(ha[rg][0]);
            float2 f1 = __half22float2(ha[rg][1]);
            s[rg][0] += f0.x + f0.y;
            s[rg][1] += f1.x + f1.y;
        }
        __syncthreads();               // all warps done with this buffer
        if (tile + 2 < 32) issue(tile + 2);
    }
#pragma unroll
    for (int rg = 0; rg < 4; rg++)
#pragma unroll
        for (int h = 0; h < 2; h++) {
            s[rg][h] += __shfl_xor_sync(0xffffffffu, s[rg][h], 1);
            s[rg][h] += __shfl_xor_sync(0xffffffffu, s[rg][h], 2);
        }
    if (lr == 0)
#pragma unroll
        for (int rg = 0; rg < 4; rg++) {
            sSum[w * 64 + rg * 16 + lq]     = s[rg][0];
            sSum[w * 64 + rg * 16 + 8 + lq] = s[rg][1];
        }
    __syncthreads();
    if (t < 64) {
        float tot = 0.f;
#pragma unroll
        for (int ww = 0; ww < 8; ww++) tot += sSum[ww * 64 + t];
        sInv[t] = 1.f / tot;
    }
    __syncthreads();

    float inv[4][2];
#pragma unroll
    for (int rg = 0; rg < 4; rg++) {
        inv[rg][0] = sInv[rg * 16 + lq];
        inv[rg][1] = sInv[rg * 16 + 8 + lq];
    }

    // ======== pass 2: values -> smem staging -> coalesced STG.128 ========
    issue(0); issue(1);
    for (int tile = 0; tile < 32; tile++) {
        int m0 = tile * TM;
        int bsel = tile & 1;
        if (bsel) { mbar_wait(mb1, ph1); ph1 ^= 1; }
        else      { mbar_wait(mb0, ph0); ph0 ^= 1; }
        __half* cur = sK + bsel * 128 * SKP;

#pragma unroll
        for (int jj = 0; jj < 2; jj++) {
            int j = j0 + jj;
            uint32_t b0[2], b1[2];
#pragma unroll
            for (int kk = 0; kk < 2; kk++) {
                b0[kk] = *(uint32_t*)&cur[(j * 8 + lq) * SKP + kk * 16 + lr * 2];
                b1[kk] = *(uint32_t*)&cur[(j * 8 + lq) * SKP + kk * 16 + lr * 2 + 8];
            }
#pragma unroll
            for (int rg = 0; rg < 4; rg++) {
                float c0 = 0.f, c1 = 0.f, c2 = 0.f, c3 = 0.f;
                mma_f16(c0, c1, c2, c3, aH[rg][0], b0[0], b1[0]);
                mma_f16(c0, c1, c2, c3, aH[rg][1], b0[1], b1[1]);
                int col = j * 8 + lr * 2;
                *(float2*)&sP[(rg * 16 + lq) * SPS + col] =
                    make_float2(ex2f(c0) * inv[rg][0], ex2f(c1) * inv[rg][0]);
                *(float2*)&sP[(rg * 16 + 8 + lq) * SPS + col] =
                    make_float2(ex2f(c2) * inv[rg][1], ex2f(c3) * inv[rg][1]);
            }
        }
        __syncthreads();               // sP complete; K buffer free
        if (tile + 2 < 32) issue(tile + 2);   // TMA overlaps the drain

        // drain [64 rows x 128 cols] coalesced: warp w covers rows w+8i
#pragma unroll
        for (int i = 0; i < 8; i++) {
            int f = t + 256 * i;
            int row = f >> 5, c4 = (f & 31) * 4;
            float4 v = *(float4*)&sP[row * SPS + c4];
            *(float4*)&att[(size_t)(b * NPIX + n0 + row) * NPIX + m0 + c4] = v;
        }
        __syncthreads();               // drain done before next tile's STS
    }
}

// ---------------------------------------------------------------------------
// Kernel C: v = Wv·sa_E + bv  (only when gamma != 0 — exact skip otherwise)
// ---------------------------------------------------------------------------
__global__ void v_kernel(const float* __restrict__ saE,
                         const float* __restrict__ Wv,
                         const float* __restrict__ bv,
                         const float* __restrict__ gamma)
{
    if (gamma[0] == 0.f) return;
    int total = BQ * CB * NPIX;
    for (int idx = blockIdx.x * blockDim.x + threadIdx.x; idx < total;
         idx += gridDim.x * blockDim.x) {
        int m  = idx & (NPIX - 1);
        int c  = (idx >> 12) & 255;
        int bb = idx >> 20;
        float s = bv[c];
        for (int cc = 0; cc < 256; cc++)
            s += Wv[c * 256 + cc] * saE[(size_t)(bb * 256 + cc) * NPIX + m];
        g_v[bb][c][m] = s;
    }
}

// ---------------------------------------------------------------------------
// Kernel D: out = gamma*(V·A^T) + sa_E.  gamma==0 -> exact copy (MLP=4)
// ---------------------------------------------------------------------------
__global__ void out_kernel(const float* __restrict__ saE,
                           const float* __restrict__ gamma,
                           float* __restrict__ out,
                           const float* __restrict__ att)
{
    float g = gamma[0];
    const int nvec = (BQ * CB * NPIX) / 4;  // 1048576 float4s
    if (g == 0.f) {
        int i = blockIdx.x * blockDim.x + threadIdx.x;   // 262144 threads
        const int stride = nvec / 4;
        float4 r[4];
#pragma unroll
        for (int k = 0; k < 4; k++) r[k] = ((const float4*)saE)[i + k * stride];
#pragma unroll
        for (int k = 0; k < 4; k++) ((float4*)out)[i + k * stride] = r[k];
    } else {
        for (int i = blockIdx.x * blockDim.x + threadIdx.x; i < nvec;
             i += gridDim.x * blockDim.x) {
            int base = i * 4;
            int n  = base & (NPIX - 1);
            int c  = (base >> 12) & 255;
            int bb = base >> 20;
            float4 e = ((const float4*)saE)[i];
            const float* vrow = &g_v[bb][c][0];
            float rr[4];
#pragma unroll
            for (int jj = 0; jj < 4; jj++) {
                const float* arow = att + (size_t)(bb * NPIX + n + jj) * NPIX;
                float s = 0.f;
                for (int m = 0; m < NPIX; m++) s += vrow[m] * arow[m];
                rr[jj] = g * s + (&e.x)[jj];
            }
            ((float4*)out)[i] = make_float4(rr[0], rr[1], rr[2], rr[3]);
        }
    }
}

// ---------------------------------------------------------------------------
extern "C" void kernel_launch(void* const* d_in, const int* in_sizes, int n_in,
                              void* d_out, int out_size)
{
    const float* saE   = (const float*)d_in[0];
    const float* saD   = (const float*)d_in[1];
    const float* Wq    = (const float*)d_in[2];
    const float* bq    = (const float*)d_in[3];
    const float* Wk    = (const float*)d_in[4];
    const float* bk    = (const float*)d_in[5];
    const float* Wv    = (const float*)d_in[6];
    const float* bv    = (const float*)d_in[7];
    const float* gamma = (const float*)d_in[8];

    float* out = (float*)d_out;
    float* att = out + (size_t)BQ * CB * NPIX;

    size_t smA = (size_t)(64 * 258 + 64 * SXS + 64) * sizeof(float);
    size_t smB = (size_t)(64 * 33 + 64 * SPS + 8 * 64 + 64) * sizeof(float)
               + (size_t)(2 * 128 * SKP) * sizeof(__half)
               + 4 * sizeof(uint64_t);   // mbarriers + pad
    cudaFuncSetAttribute(qk_kernel,   cudaFuncAttributeMaxDynamicSharedMemorySize, (int)smA);
    cudaFuncSetAttribute(attn_kernel, cudaFuncAttributeMaxDynamicSharedMemorySize, (int)smB);

    qk_kernel<<<dim3(64, 4), 256, smA>>>(saD, Wq, bq, Wk, bk);
    attn_kernel<<<dim3(64, 4), 256, smB>>>(att);
    v_kernel<<<1024, 256>>>(saE, Wv, bv, gamma);
    out_kernel<<<1024, 256>>>(saE, gamma, out, att);
}

// round 13
// speedup vs baseline: 1.0921x; 1.0921x over previous
#include <cuda_runtime.h>
#include <cuda_fp16.h>
#include <cstdint>

#define NPIX 4096
#define CB   256
#define BQ   4
#define TM   128
#define SKP  32    // packed fp16 K-tile stride in halves (bulk-copy layout)
#define SXS  68    // qk saD-chunk stride (floats)
#define NBUF 4     // TMA ring depth

// Scratch (device globals — no runtime allocation allowed)
__device__ float  g_qk[BQ][32][NPIX];        // q (float), [d][n]
__device__ __half g_kh[BQ][NPIX][32];        // k transposed [m][d], fp16 (1 MB)
__device__ float  g_v[BQ][CB][NPIX];         // only when gamma != 0

#define LOG2E 1.4426950408889634f

__device__ __forceinline__ float tf32r(float v) {
    uint32_t u;
    asm("cvt.rna.tf32.f32 %0, %1;" : "=r"(u) : "f"(v));
    return __uint_as_float(u);
}
__device__ __forceinline__ float ex2f(float x) {
    float r;
    asm("ex2.approx.f32 %0, %1;" : "=f"(r) : "f"(x));
    return r;
}

// ---- bulk-copy + mbarrier primitives ----
__device__ __forceinline__ uint32_t s2u(const void* p) {
    return (uint32_t)__cvta_generic_to_shared(p);
}
__device__ __forceinline__ void mbar_init(uint32_t a, uint32_t cnt) {
    asm volatile("mbarrier.init.shared.b64 [%0], %1;" :: "r"(a), "r"(cnt) : "memory");
}
__device__ __forceinline__ void mbar_expect_tx(uint32_t a, uint32_t bytes) {
    asm volatile("mbarrier.arrive.expect_tx.shared.b64 _, [%0], %1;"
                 :: "r"(a), "r"(bytes) : "memory");
}
__device__ __forceinline__ void bulk_g2s(uint32_t sdst, const void* g,
                                         uint32_t bytes, uint32_t mbar) {
    asm volatile(
        "cp.async.bulk.shared::cta.global.mbarrier::complete_tx::bytes "
        "[%0], [%1], %2, [%3];"
        :: "r"(sdst), "l"(g), "r"(bytes), "r"(mbar) : "memory");
}
__device__ __forceinline__ void mbar_wait(uint32_t a, uint32_t parity) {
    asm volatile(
        "{\n\t.reg .pred P;\n"
        "W%=:\n\tmbarrier.try_wait.parity.acquire.cta.shared::cta.b64 P, [%0], %1, 0x989680;\n"
        "\t@P bra D%=;\n\tbra W%=;\n"
        "D%=:\n\t}\n"
        :: "r"(a), "r"(parity) : "memory");
}

// ---- mma helpers ----
__device__ __forceinline__ void mma_tf32(float& c0, float& c1, float& c2, float& c3,
                                         const float a[4], float b0, float b1)
{
    asm volatile(
        "mma.sync.aligned.m16n8k8.row.col.f32.tf32.tf32.f32 "
        "{%0,%1,%2,%3}, {%4,%5,%6,%7}, {%8,%9}, {%0,%1,%2,%3};"
        : "+f"(c0), "+f"(c1), "+f"(c2), "+f"(c3)
        : "r"(__float_as_uint(a[0])), "r"(__float_as_uint(a[1])),
          "r"(__float_as_uint(a[2])), "r"(__float_as_uint(a[3])),
          "r"(__float_as_uint(b0)), "r"(__float_as_uint(b1)));
}
__device__ __forceinline__ void mma_f16(float& c0, float& c1, float& c2, float& c3,
                                        const uint32_t a[4], uint32_t b0, uint32_t b1)
{
    asm volatile(
        "mma.sync.aligned.m16n8k16.row.col.f32.f16.f16.f32 "
        "{%0,%1,%2,%3}, {%4,%5,%6,%7}, {%8,%9}, {%0,%1,%2,%3};"
        : "+f"(c0), "+f"(c1), "+f"(c2), "+f"(c3)
        : "r"(a[0]), "r"(a[1]), "r"(a[2]), "r"(a[3]), "r"(b0), "r"(b1));
}
// f16 accumulators: D = {row lq (2 halves), row lq+8 (2 halves)}
__device__ __forceinline__ void mma_f16acc(uint32_t& d0, uint32_t& d1,
                                           const uint32_t a[4], uint32_t b0, uint32_t b1)
{
    asm volatile(
        "mma.sync.aligned.m16n8k16.row.col.f16.f16.f16.f16 "
        "{%0,%1}, {%2,%3,%4,%5}, {%6,%7}, {%0,%1};"
        : "+r"(d0), "+r"(d1)
        : "r"(a[0]), "r"(a[1]), "r"(a[2]), "r"(a[3]), "r"(b0), "r"(b1));
}
__device__ __forceinline__ uint32_t packh(float lo, float hi) {
    __half2 h = __floats2half2_rn(lo, hi);
    return *(uint32_t*)&h;
}

// ---------------------------------------------------------------------------
// Kernel A (tf32 mma): q = Wq·sa_D + bq (float, [d][n]),
//                      k = Wk·sa_D + bk (fp16, [m][d] transposed)
// ---------------------------------------------------------------------------
__global__ __launch_bounds__(256, 2) void qk_kernel(
    const float* __restrict__ saD,
    const float* __restrict__ Wq, const float* __restrict__ bq,
    const float* __restrict__ Wk, const float* __restrict__ bk)
{
    extern __shared__ float sm[];
    float* sW = sm;                 // 64 x 258 (tf32-rounded W)
    float* sX = sm + 64 * 258;      // 64 x SXS (tf32-rounded saD chunk)

    int b  = blockIdx.y;
    int n0 = blockIdx.x * 64;
    int t  = threadIdx.x, w = t >> 5, l = t & 31;
    int lq = l >> 2, lr = l & 3;
    int wd = w & 3, wn = w >> 2;

    for (int i = t; i < 64 * 256; i += 256) {
        int d = i >> 8, c = i & 255;
        float v = (d < 32) ? Wq[d * 256 + c] : Wk[(d - 32) * 256 + c];
        sW[d * 258 + c] = tf32r(v);
    }
    __syncthreads();

    float acc[4][4];
#pragma unroll
    for (int j = 0; j < 4; j++)
#pragma unroll
        for (int i = 0; i < 4; i++) acc[j][i] = 0.f;

    for (int c0 = 0; c0 < 256; c0 += 64) {
        __syncthreads();
#pragma unroll
        for (int r = 0; r < 4; r++) {
            int f  = t + 256 * r;
            int cc = f >> 4, nn = (f & 15) << 2;
            float4 v = *(const float4*)&saD[(size_t)(b * 256 + c0 + cc) * NPIX + n0 + nn];
            v.x = tf32r(v.x); v.y = tf32r(v.y); v.z = tf32r(v.z); v.w = tf32r(v.w);
            *(float4*)&sX[cc * SXS + nn] = v;
        }
        __syncthreads();
#pragma unroll
        for (int kk = 0; kk < 8; kk++) {
            int ca = c0 + kk * 8;
            float a[4];
            a[0] = sW[(wd * 16 + lq) * 258 + ca + lr];
            a[1] = sW[(wd * 16 + 8 + lq) * 258 + ca + lr];
            a[2] = sW[(wd * 16 + lq) * 258 + ca + lr + 4];
            a[3] = sW[(wd * 16 + 8 + lq) * 258 + ca + lr + 4];
#pragma unroll
            for (int j = 0; j < 4; j++) {
                float b0 = sX[(kk * 8 + lr) * SXS + wn * 32 + j * 8 + lq];
                float b1 = sX[(kk * 8 + lr + 4) * SXS + wn * 32 + j * 8 + lq];
                mma_tf32(acc[j][0], acc[j][1], acc[j][2], acc[j][3], a, b0, b1);
            }
        }
    }

    // q epilogue (wd 0,1 -> d rows 0..31)
    if (wd < 2) {
        int d = wd * 16 + lq;
        float bias0 = bq[d], bias1 = bq[d + 8];
#pragma unroll
        for (int j = 0; j < 4; j++) {
            int n = n0 + wn * 32 + j * 8 + lr * 2;
            *(float2*)&g_qk[b][d][n] =
                make_float2(acc[j][0] + bias0, acc[j][1] + bias0);
            *(float2*)&g_qk[b][d + 8][n] =
                make_float2(acc[j][2] + bias1, acc[j][3] + bias1);
        }
    }

    // k epilogue: stage fp16 [n][d] in smem (reuse sX), coalesced out
    __syncthreads();
    __half* sT = (__half*)sX;   // 64 x 40 halves
    if (wd >= 2) {
        int dk = (wd - 2) * 16 + lq;
        float bias0 = bk[dk], bias1 = bk[dk + 8];
#pragma unroll
        for (int j = 0; j < 4; j++) {
            int nl = wn * 32 + j * 8 + lr * 2;
            sT[nl * 40 + dk]           = __float2half(acc[j][0] + bias0);
            sT[(nl + 1) * 40 + dk]     = __float2half(acc[j][1] + bias0);
            sT[nl * 40 + dk + 8]       = __float2half(acc[j][2] + bias1);
            sT[(nl + 1) * 40 + dk + 8] = __float2half(acc[j][3] + bias1);
        }
    }
    __syncthreads();
    {
        int r = t >> 2, p = t & 3;
        uint4 v = *(uint4*)&sT[r * 40 + p * 8];
        *(uint4*)&g_kh[b][n0 + r][p * 8] = v;
    }
}

// ---------------------------------------------------------------------------
// Kernel B: fused energy + softmax + attention (R10 compute structure).
// QUAD-buffered bulk-TMA K tiles (depth-4 ring hides copy latency).
// Pass 1: f16-accum mma -> h2exp2. Pass 2: f32 mma + ex2, direct stores.
// Tail: CTA copies its 4096-float4 slice of sa_E -> out (gamma==0 output).
// ---------------------------------------------------------------------------
__global__ __launch_bounds__(256, 2) void attn_kernel(
    float* __restrict__ att,
    const float* __restrict__ saE,
    float* __restrict__ outp)
{
    extern __shared__ float sm[];
    float*  sQ   = sm;                            // 64*33 floats
    __half* sK   = (__half*)(sm + 64 * 33);       // NBUF x 128*SKP halves (32 KB)
    float*  sSum = (float*)(sK + NBUF * 128 * SKP);  // 8*64
    float*  sInv = sSum + 8 * 64;                 // 64
    uint64_t* mbars = (uint64_t*)(sInv + 64);     // NBUF mbarriers

    int b  = blockIdx.y;
    int n0 = blockIdx.x * 64;
    int t  = threadIdx.x, w = t >> 5, l = t & 31;
    int lq = l >> 2, lr = l & 3;
    int j0 = 2 * w;

    const float*  qg  = &g_qk[b][0][0];
    const __half* khg = &g_kh[b][0][0];

    uint32_t mbbase = s2u(&mbars[0]);
    uint32_t skbase = s2u(sK);

    if (t == 0)
#pragma unroll
        for (int i = 0; i < NBUF; i++) mbar_init(mbbase + i * 8, 1);

    // Q tile [64 n][32 d], transposed, pre-scaled by log2e
    for (int i = t; i < 64 * 32; i += 256) {
        int n = i & 63, d = i >> 6;
        sQ[n * 33 + d] = qg[(size_t)d * NPIX + n0 + n] * LOG2E;
    }
    __syncthreads();   // covers mbarrier init + sQ

    auto issue = [&](int tile) {
        if (t == 0) {
            int bsel = tile & (NBUF - 1);
            mbar_expect_tx(mbbase + bsel * 8, 8192);
            bulk_g2s(skbase + bsel * 8192, khg + (size_t)tile * TM * SKP,
                     8192, mbbase + bsel * 8);
        }
    };

    uint32_t ph = 0;   // per-buffer parity bits

#pragma unroll
    for (int i = 0; i < NBUF; i++) issue(i);

    // A fragments fp16: 4 row-groups x 2 k16-chunks x 4 regs (both passes)
    uint32_t aH[4][2][4];
#pragma unroll
    for (int rg = 0; rg < 4; rg++) {
        int r = rg * 16 + lq;
#pragma unroll
        for (int kk = 0; kk < 2; kk++) {
            int c = kk * 16 + lr * 2;
            aH[rg][kk][0] = packh(sQ[r * 33 + c],           sQ[r * 33 + c + 1]);
            aH[rg][kk][1] = packh(sQ[(r + 8) * 33 + c],     sQ[(r + 8) * 33 + c + 1]);
            aH[rg][kk][2] = packh(sQ[r * 33 + c + 8],       sQ[r * 33 + c + 9]);
            aH[rg][kk][3] = packh(sQ[(r + 8) * 33 + c + 8], sQ[(r + 8) * 33 + c + 9]);
        }
    }

    // ======== pass 1: denominators (f16-accum mma -> h2exp2 direct) ========
    float s[4][2];
#pragma unroll
    for (int rg = 0; rg < 4; rg++) s[rg][0] = s[rg][1] = 0.f;

    for (int tile = 0; tile < 32; tile++) {
        int bsel = tile & (NBUF - 1);
        mbar_wait(mbbase + bsel * 8, (ph >> bsel) & 1);
        ph ^= 1u << bsel;
        __half* cur = sK + bsel * 128 * SKP;

        __half2 ha[4][2];
#pragma unroll
        for (int rg = 0; rg < 4; rg++) {
            ha[rg][0] = __floats2half2_rn(0.f, 0.f);
            ha[rg][1] = __floats2half2_rn(0.f, 0.f);
        }
#pragma unroll
        for (int jj = 0; jj < 2; jj++) {
            int j = j0 + jj;
            uint32_t b0[2], b1[2];
#pragma unroll
            for (int kk = 0; kk < 2; kk++) {
                b0[kk] = *(uint32_t*)&cur[(j * 8 + lq) * SKP + kk * 16 + lr * 2];
                b1[kk] = *(uint32_t*)&cur[(j * 8 + lq) * SKP + kk * 16 + lr * 2 + 8];
            }
#pragma unroll
            for (int rg = 0; rg < 4; rg++) {
                uint32_t d0 = 0, d1 = 0;
                mma_f16acc(d0, d1, aH[rg][0], b0[0], b1[0]);
                mma_f16acc(d0, d1, aH[rg][1], b0[1], b1[1]);
                ha[rg][0] = __hadd2(ha[rg][0], h2exp2(*(__half2*)&d0));
                ha[rg][1] = __hadd2(ha[rg][1], h2exp2(*(__half2*)&d1));
            }
        }
#pragma unroll
        for (int rg = 0; rg < 4; rg++) {
            float2 f0 = __half22float2(ha[rg][0]);
            float2 f1 = __half22float2(ha[rg][1]);
            s[rg][0] += f0.x + f0.y;
            s[rg][1] += f1.x + f1.y;
        }
        __syncthreads();               // all warps done with this buffer
        if (tile + NBUF < 32) issue(tile + NBUF);
    }
#pragma unroll
    for (int rg = 0; rg < 4; rg++)
#pragma unroll
        for (int h = 0; h < 2; h++) {
            s[rg][h] += __shfl_xor_sync(0xffffffffu, s[rg][h], 1);
            s[rg][h] += __shfl_xor_sync(0xffffffffu, s[rg][h], 2);
        }
    if (lr == 0)
#pragma unroll
        for (int rg = 0; rg < 4; rg++) {
            sSum[w * 64 + rg * 16 + lq]     = s[rg][0];
            sSum[w * 64 + rg * 16 + 8 + lq] = s[rg][1];
        }
    __syncthreads();
    if (t < 64) {
        float tot = 0.f;
#pragma unroll
        for (int ww = 0; ww < 8; ww++) tot += sSum[ww * 64 + t];
        sInv[t] = 1.f / tot;
    }
    __syncthreads();

    float inv[4][2];
#pragma unroll
    for (int rg = 0; rg < 4; rg++) {
        inv[rg][0] = sInv[rg * 16 + lq];
        inv[rg][1] = sInv[rg * 16 + 8 + lq];
    }

    // ======== pass 2: values (f32 ex2), direct float2 stores ========
    // ph bits are back to 0 here (each buffer toggled 8x in pass 1).
#pragma unroll
    for (int i = 0; i < NBUF; i++) issue(i);

    for (int tile = 0; tile < 32; tile++) {
        int m0 = tile * TM;
        int bsel = tile & (NBUF - 1);
        mbar_wait(mbbase + bsel * 8, (ph >> bsel) & 1);
        ph ^= 1u << bsel;
        __half* cur = sK + bsel * 128 * SKP;
#pragma unroll
        for (int jj = 0; jj < 2; jj++) {
            int j = j0 + jj;
            uint32_t b0[2], b1[2];
#pragma unroll
            for (int kk = 0; kk < 2; kk++) {
                b0[kk] = *(uint32_t*)&cur[(j * 8 + lq) * SKP + kk * 16 + lr * 2];
                b1[kk] = *(uint32_t*)&cur[(j * 8 + lq) * SKP + kk * 16 + lr * 2 + 8];
            }
#pragma unroll
            for (int rg = 0; rg < 4; rg++) {
                float c0 = 0.f, c1 = 0.f, c2 = 0.f, c3 = 0.f;
                mma_f16(c0, c1, c2, c3, aH[rg][0], b0[0], b1[0]);
                mma_f16(c0, c1, c2, c3, aH[rg][1], b0[1], b1[1]);
                float p0 = ex2f(c0) * inv[rg][0];
                float p1 = ex2f(c1) * inv[rg][0];
                float p2 = ex2f(c2) * inv[rg][1];
                float p3 = ex2f(c3) * inv[rg][1];
                size_t base = ((size_t)(b * NPIX + n0 + rg * 16 + lq)) * NPIX
                              + m0 + j * 8 + lr * 2;
                *(float2*)&att[base]            = make_float2(p0, p1);
                *(float2*)&att[base + 8 * NPIX] = make_float2(p2, p3);
            }
        }
        __syncthreads();
        if (tile + NBUF < 32) issue(tile + NBUF);
    }

    // ======== tail: copy this CTA's slice of sa_E -> out ========
    // out is 1,048,576 float4 total; 256 CTAs -> 4096 float4 each.
    {
        int cta = b * 64 + blockIdx.x;             // 0..255
        const float4* src = (const float4*)saE + (size_t)cta * 4096;
        float4*       dst = (float4*)outp + (size_t)cta * 4096;
#pragma unroll
        for (int i = 0; i < 16; i++)
            dst[i * 256 + t] = src[i * 256 + t];
    }
}

// ---------------------------------------------------------------------------
// Kernel C: v = Wv·sa_E + bv  (only when gamma != 0 — exact skip otherwise)
// ---------------------------------------------------------------------------
__global__ void v_kernel(const float* __restrict__ saE,
                         const float* __restrict__ Wv,
                         const float* __restrict__ bv,
                         const float* __restrict__ gamma)
{
    if (gamma[0] == 0.f) return;
    int total = BQ * CB * NPIX;
    for (int idx = blockIdx.x * blockDim.x + threadIdx.x; idx < total;
         idx += gridDim.x * blockDim.x) {
        int m  = idx & (NPIX - 1);
        int c  = (idx >> 12) & 255;
        int bb = idx >> 20;
        float s = bv[c];
        for (int cc = 0; cc < 256; cc++)
            s += Wv[c * 256 + cc] * saE[(size_t)(bb * 256 + cc) * NPIX + m];
        g_v[bb][c][m] = s;
    }
}

// ---------------------------------------------------------------------------
// Kernel D: gamma != 0 only: out = gamma*(V·A^T) + sa_E (overwrites copy).
// ---------------------------------------------------------------------------
__global__ void out_kernel(const float* __restrict__ saE,
                           const float* __restrict__ gamma,
                           float* __restrict__ out,
                           const float* __restrict__ att)
{
    float g = gamma[0];
    if (g == 0.f) return;
    const int nvec = (BQ * CB * NPIX) / 4;
    for (int i = blockIdx.x * blockDim.x + threadIdx.x; i < nvec;
         i += gridDim.x * blockDim.x) {
        int base = i * 4;
        int n  = base & (NPIX - 1);
        int c  = (base >> 12) & 255;
        int bb = base >> 20;
        float4 e = ((const float4*)saE)[i];
        const float* vrow = &g_v[bb][c][0];
        float rr[4];
#pragma unroll
        for (int jj = 0; jj < 4; jj++) {
            const float* arow = att + (size_t)(bb * NPIX + n + jj) * NPIX;
            float s = 0.f;
            for (int m = 0; m < NPIX; m++) s += vrow[m] * arow[m];
            rr[jj] = g * s + (&e.x)[jj];
        }
        ((float4*)out)[i] = make_float4(rr[0], rr[1], rr[2], rr[3]);
    }
}

// ---------------------------------------------------------------------------
extern "C" void kernel_launch(void* const* d_in, const int* in_sizes, int n_in,
                              void* d_out, int out_size)
{
    const float* saE   = (const float*)d_in[0];
    const float* saD   = (const float*)d_in[1];
    const float* Wq    = (const float*)d_in[2];
    const float* bq    = (const float*)d_in[3];
    const float* Wk    = (const float*)d_in[4];
    const float* bk    = (const float*)d_in[5];
    const float* Wv    = (const float*)d_in[6];
    const float* bv    = (const float*)d_in[7];
    const float* gamma = (const float*)d_in[8];

    float* out = (float*)d_out;
    float* att = out + (size_t)BQ * CB * NPIX;

    size_t smA = (size_t)(64 * 258 + 64 * SXS + 64) * sizeof(float);
    size_t smB = (size_t)(64 * 33 + 8 * 64 + 64) * sizeof(float)
               + (size_t)(NBUF * 128 * SKP) * sizeof(__half)
               + (NBUF + 2) * sizeof(uint64_t);   // mbarriers + pad
    cudaFuncSetAttribute(qk_kernel,   cudaFuncAttributeMaxDynamicSharedMemorySize, (int)smA);
    cudaFuncSetAttribute(attn_kernel, cudaFuncAttributeMaxDynamicSharedMemorySize, (int)smB);

    qk_kernel<<<dim3(64, 4), 256, smA>>>(saD, Wq, bq, Wk, bk);
    attn_kernel<<<dim3(64, 4), 256, smB>>>(att, saE, out);
    v_kernel<<<1024, 256>>>(saE, Wv, bv, gamma);
    out_kernel<<<1024, 256>>>(saE, gamma, out, att);
}